// round 2
// baseline (speedup 1.0000x reference)
#include <cuda_runtime.h>
#include <math.h>

// Problem constants
#define BD   64      // batch
#define CD   256     // channels == sketch dim D
#define ATTR 300
#define HWD  784     // 28*28
#define O1   32      // conv1 output channels
#define TILE 64      // spatial tile per CTA in K3

// Scratch (no cudaMalloc allowed)
__device__ float g_SX[BD * CD];          // per-batch sketch of embedding
__device__ float g_N[BD * CD * O1];      // folded [b][c][o] matrix, o contiguous

// ---------------------------------------------------------------------------
// K1: emb = attr_one_hot @ W_emb^T + b_emb ; sx = count_sketch(emb, h1, s1)
// One block per batch, 256 threads. Deterministic (no atomics): thread m scans
// all j and accumulates matching buckets.
// ---------------------------------------------------------------------------
__global__ void k1_sketch(const float* __restrict__ attr_one_hot,
                          const float* __restrict__ W_emb,
                          const float* __restrict__ b_emb,
                          const int*   __restrict__ h1,
                          const float* __restrict__ s1) {
    __shared__ float attr_sm[ATTR];
    __shared__ float emb_sm[CD];
    __shared__ int   h1_sm[CD];
    __shared__ float s1_sm[CD];

    const int b = blockIdx.x;
    const int j = threadIdx.x;

    for (int a = j; a < ATTR; a += 256) attr_sm[a] = attr_one_hot[b * ATTR + a];
    h1_sm[j] = h1[j];
    s1_sm[j] = s1[j];
    __syncthreads();

    float acc = b_emb[j];
    const float* wrow = W_emb + (size_t)j * ATTR;
#pragma unroll 4
    for (int a = 0; a < ATTR; a++) acc += attr_sm[a] * wrow[a];
    emb_sm[j] = acc;
    __syncthreads();

    const int m = j;
    float sx = 0.f;
#pragma unroll 8
    for (int jj = 0; jj < CD; jj++)
        sx += (h1_sm[jj] == m) ? s1_sm[jj] * emb_sm[jj] : 0.f;
    g_SX[b * CD + m] = sx;
}

// ---------------------------------------------------------------------------
// K2: M_b[o,m] = sum_j sx_b[j] * conv1_w[o, (m+j) mod 256]
//     N_b[o,c] = s2[c] * M_b[o, h2[c]]
// grid (64 batches, 8 o-groups of 4), 256 threads (thread = m, then = c).
// ---------------------------------------------------------------------------
__global__ void k2_buildN(const float* __restrict__ conv1_w,
                          const int*   __restrict__ h2,
                          const float* __restrict__ s2) {
    __shared__ float sx[CD];
    __shared__ float wext[4][512];
    __shared__ float Msm[4][CD];

    const int b   = blockIdx.x;
    const int og  = blockIdx.y;     // 0..7
    const int tid = threadIdx.x;    // 0..255

    sx[tid] = g_SX[b * CD + tid];
#pragma unroll
    for (int oo = 0; oo < 4; oo++) {
        float w = conv1_w[(og * 4 + oo) * CD + tid];
        wext[oo][tid]       = w;
        wext[oo][tid + 256] = w;
    }
    __syncthreads();

    float a0 = 0.f, a1 = 0.f, a2 = 0.f, a3 = 0.f;
#pragma unroll 8
    for (int jj = 0; jj < CD; jj++) {
        float s = sx[jj];
        a0 += s * wext[0][tid + jj];
        a1 += s * wext[1][tid + jj];
        a2 += s * wext[2][tid + jj];
        a3 += s * wext[3][tid + jj];
    }
    Msm[0][tid] = a0; Msm[1][tid] = a1; Msm[2][tid] = a2; Msm[3][tid] = a3;
    __syncthreads();

    const int   c  = tid;
    const int   hc = h2[c];
    const float sc = s2[c];
    float* np = &g_N[((size_t)b * CD + c) * O1 + og * 4];
    np[0] = sc * Msm[0][hc];
    np[1] = sc * Msm[1][hc];
    np[2] = sc * Msm[2][hc];
    np[3] = sc * Msm[3][hc];
}

// ---------------------------------------------------------------------------
// K3 (fused): hidden = relu(N_b @ X), attr_map = sigmoid(c2 . hidden),
//             attr_feature = attr_map * X.   X tile kept in smem (read once).
// grid (13 tiles, 64 batches), 128 threads. Thread layout 16 t-groups x 8
// o-groups, each thread a 4x4 register tile -> 16 FMA per 2 LDS.128.
// ---------------------------------------------------------------------------
__global__ void __launch_bounds__(128, 2)
k3_fused(const float* __restrict__ ef,
         const float* __restrict__ conv2_w,
         float* __restrict__ out_map,
         float* __restrict__ out_feat) {
    extern __shared__ float smem[];
    float* Xs   = smem;                 // [256][64]
    float* Ns   = Xs + CD * TILE;       // [256][32]
    float* red  = Ns + CD * O1;         // [8][64]
    float* amap = red + 8 * TILE;       // [64]

    const int b   = blockIdx.y;
    const int hw0 = blockIdx.x * TILE;
    const int tid = threadIdx.x;

    // Load folded matrix N (32 KB, contiguous, coalesced): 2048 float4 / 128 thr
    {
        const float4* ng  = (const float4*)(g_N + (size_t)b * CD * O1);
        float4*       ns4 = (float4*)Ns;
#pragma unroll
        for (int i = 0; i < 16; i++)
            ns4[tid + i * 128] = ng[tid + i * 128];
    }

    // Load X tile: ef[b, c, hw0 : hw0+64] -> Xs[c][t]. 4096 float4 / 128 thr.
    const float* efb = ef + (size_t)b * CD * HWD;
#pragma unroll
    for (int k = 0; k < 32; k++) {
        int idx = tid + k * 128;          // 0..4095
        int c   = idx >> 4;               // 0..255
        int t   = (idx & 15) * 4;         // 0..60
        float4 v = make_float4(0.f, 0.f, 0.f, 0.f);
        if (hw0 + t < HWD) v = *(const float4*)(efb + (size_t)c * HWD + hw0 + t);
        *(float4*)(Xs + c * TILE + t) = v;
    }
    __syncthreads();

    const int tt = tid & 15;   // t-group: owns t = tt*4 .. tt*4+3
    const int oo = tid >> 4;   // o-group: owns o = oo*4 .. oo*4+3

    float acc[4][4];
#pragma unroll
    for (int i = 0; i < 4; i++)
#pragma unroll
        for (int jj = 0; jj < 4; jj++) acc[i][jj] = 0.f;

#pragma unroll 8
    for (int c = 0; c < CD; c++) {
        float4 xv = *(const float4*)(Xs + c * TILE + tt * 4);
        float4 nv = *(const float4*)(Ns + c * O1 + oo * 4);
        acc[0][0] += nv.x * xv.x; acc[0][1] += nv.x * xv.y;
        acc[0][2] += nv.x * xv.z; acc[0][3] += nv.x * xv.w;
        acc[1][0] += nv.y * xv.x; acc[1][1] += nv.y * xv.y;
        acc[1][2] += nv.y * xv.z; acc[1][3] += nv.y * xv.w;
        acc[2][0] += nv.z * xv.x; acc[2][1] += nv.z * xv.y;
        acc[2][2] += nv.z * xv.z; acc[2][3] += nv.z * xv.w;
        acc[3][0] += nv.w * xv.x; acc[3][1] += nv.w * xv.y;
        acc[3][2] += nv.w * xv.z; acc[3][3] += nv.w * xv.w;
    }

    // relu + conv2 partial over this thread's 4 o's, for its 4 t's
    float c2[4];
#pragma unroll
    for (int i = 0; i < 4; i++) c2[i] = __ldg(conv2_w + oo * 4 + i);

    float p[4] = {0.f, 0.f, 0.f, 0.f};
#pragma unroll
    for (int i = 0; i < 4; i++)
#pragma unroll
        for (int jj = 0; jj < 4; jj++)
            p[jj] += c2[i] * fmaxf(acc[i][jj], 0.f);

#pragma unroll
    for (int jj = 0; jj < 4; jj++) red[oo * TILE + tt * 4 + jj] = p[jj];
    __syncthreads();

    // Reduce 8 o-groups, sigmoid, emit attr_map
    if (tid < TILE) {
        float s = 0.f;
#pragma unroll
        for (int g = 0; g < 8; g++) s += red[g * TILE + tid];
        float am = 1.f / (1.f + expf(-s));
        amap[tid] = am;
        if (hw0 + tid < HWD) out_map[b * HWD + hw0 + tid] = am;
    }
    __syncthreads();

    // attr_feature = attr_map * X, from the smem tile (no second global read)
    float* ofb = out_feat + (size_t)b * CD * HWD;
#pragma unroll
    for (int k = 0; k < 32; k++) {
        int idx = tid + k * 128;
        int c   = idx >> 4;
        int t   = (idx & 15) * 4;
        if (hw0 + t < HWD) {
            float4 v  = *(const float4*)(Xs + c * TILE + t);
            float  a0 = amap[t],     a1 = amap[t + 1];
            float  a2 = amap[t + 2], a3 = amap[t + 3];
            *(float4*)(ofb + (size_t)c * HWD + hw0 + t) =
                make_float4(v.x * a0, v.y * a1, v.z * a2, v.w * a3);
        }
    }
}

// ---------------------------------------------------------------------------
extern "C" void kernel_launch(void* const* d_in, const int* in_sizes, int n_in,
                              void* d_out, int out_size) {
    const float* entity  = (const float*)d_in[0];   // [64,256,28,28]
    const float* attr1h  = (const float*)d_in[1];   // [64,300]
    const float* W_emb   = (const float*)d_in[2];   // [256,300]
    const float* b_emb   = (const float*)d_in[3];   // [256]
    const int*   h1      = (const int*)  d_in[4];   // [256]
    const float* s1      = (const float*)d_in[5];   // [256]
    const int*   h2      = (const int*)  d_in[6];   // [256]
    const float* s2      = (const float*)d_in[7];   // [256]
    const float* conv1_w = (const float*)d_in[8];   // [32,256]
    const float* conv2_w = (const float*)d_in[9];   // [1,32]

    float* out_map  = (float*)d_out;                      // [64,1,28,28]
    float* out_feat = (float*)d_out + (size_t)BD * HWD;   // [64,256,28,28]

    const int k3_smem = (CD * TILE + CD * O1 + 8 * TILE + TILE) * (int)sizeof(float);
    cudaFuncSetAttribute(k3_fused, cudaFuncAttributeMaxDynamicSharedMemorySize, k3_smem);

    k1_sketch<<<BD, 256>>>(attr1h, W_emb, b_emb, h1, s1);
    k2_buildN<<<dim3(BD, 8), 256>>>(conv1_w, h2, s2);
    k3_fused<<<dim3((HWD + TILE - 1) / TILE, BD), 128, k3_smem>>>(entity, conv2_w, out_map, out_feat);
}

// round 3
// speedup vs baseline: 1.1659x; 1.1659x over previous
#include <cuda_runtime.h>
#include <math.h>

// Problem constants
#define BD   64      // batch
#define CD   256     // channels == sketch dim D
#define ATTR 300
#define HWD  784     // 28*28
#define O1   32      // conv1 output channels
#define TILE 64      // spatial tile per CTA in K3

// Scratch (no cudaMalloc allowed)
__device__ float g_SX[BD * CD];          // per-batch sketch of embedding
__device__ float g_N[BD * CD * O1];      // folded [b][c][o] matrix, o contiguous

// ---------------------------------------------------------------------------
// K1: emb = attr_one_hot @ W_emb^T + b_emb ; sx = count_sketch(emb, h1, s1)
// One block per batch, 256 threads = 8 warps. Warp w owns j in [32w, 32w+32);
// lanes split the 300-dim dot product (coalesced W_emb reads), 2 j's in
// flight per iteration for MLP, butterfly-reduce.
// ---------------------------------------------------------------------------
__global__ void k1_sketch(const float* __restrict__ attr_one_hot,
                          const float* __restrict__ W_emb,
                          const float* __restrict__ b_emb,
                          const int*   __restrict__ h1,
                          const float* __restrict__ s1) {
    __shared__ float attr_sm[ATTR];
    __shared__ float emb_sm[CD];
    __shared__ int   h1_sm[CD];
    __shared__ float s1_sm[CD];

    const int b    = blockIdx.x;
    const int tid  = threadIdx.x;
    const int lane = tid & 31;
    const int wrp  = tid >> 5;

    for (int a = tid; a < ATTR; a += 256) attr_sm[a] = attr_one_hot[b * ATTR + a];
    h1_sm[tid] = h1[tid];
    s1_sm[tid] = s1[tid];
    __syncthreads();

    const int jbase = wrp * 32;
#pragma unroll
    for (int jr = 0; jr < 32; jr += 2) {
        const int j0 = jbase + jr;
        const int j1 = j0 + 1;
        const float* w0 = W_emb + (size_t)j0 * ATTR;
        const float* w1 = W_emb + (size_t)j1 * ATTR;
        float p0 = 0.f, p1 = 0.f;
        for (int a = lane; a < ATTR; a += 32) {      // coalesced across lanes
            float av = attr_sm[a];
            p0 += av * w0[a];
            p1 += av * w1[a];
        }
#pragma unroll
        for (int off = 16; off >= 1; off >>= 1) {
            p0 += __shfl_xor_sync(0xFFFFFFFFu, p0, off);
            p1 += __shfl_xor_sync(0xFFFFFFFFu, p1, off);
        }
        if (lane == 0) {
            emb_sm[j0] = p0 + b_emb[j0];
            emb_sm[j1] = p1 + b_emb[j1];
        }
    }
    __syncthreads();

    // Deterministic count-sketch: thread m scans all j for h1[j]==m.
    const int m = tid;
    float sx = 0.f;
#pragma unroll 8
    for (int jj = 0; jj < CD; jj++)
        sx += (h1_sm[jj] == m) ? s1_sm[jj] * emb_sm[jj] : 0.f;
    g_SX[b * CD + m] = sx;
}

// ---------------------------------------------------------------------------
// K2: M_b[o,m] = sum_j sx_b[j] * conv1_w[o, (m+j) mod 256]
//     N_b[o,c] = s2[c] * M_b[o, h2[c]]
// grid (64 batches, 8 o-groups of 4), 256 threads (thread = m, then = c).
// ---------------------------------------------------------------------------
__global__ void k2_buildN(const float* __restrict__ conv1_w,
                          const int*   __restrict__ h2,
                          const float* __restrict__ s2) {
    __shared__ float sx[CD];
    __shared__ float wext[4][512];
    __shared__ float Msm[4][CD];

    const int b   = blockIdx.x;
    const int og  = blockIdx.y;     // 0..7
    const int tid = threadIdx.x;    // 0..255

    sx[tid] = g_SX[b * CD + tid];
#pragma unroll
    for (int oo = 0; oo < 4; oo++) {
        float w = conv1_w[(og * 4 + oo) * CD + tid];
        wext[oo][tid]       = w;
        wext[oo][tid + 256] = w;
    }
    __syncthreads();

    float a0 = 0.f, a1 = 0.f, a2 = 0.f, a3 = 0.f;
#pragma unroll 8
    for (int jj = 0; jj < CD; jj++) {
        float s = sx[jj];
        a0 += s * wext[0][tid + jj];
        a1 += s * wext[1][tid + jj];
        a2 += s * wext[2][tid + jj];
        a3 += s * wext[3][tid + jj];
    }
    Msm[0][tid] = a0; Msm[1][tid] = a1; Msm[2][tid] = a2; Msm[3][tid] = a3;
    __syncthreads();

    const int   c  = tid;
    const int   hc = h2[c];
    const float sc = s2[c];
    float* np = &g_N[((size_t)b * CD + c) * O1 + og * 4];
    np[0] = sc * Msm[0][hc];
    np[1] = sc * Msm[1][hc];
    np[2] = sc * Msm[2][hc];
    np[3] = sc * Msm[3][hc];
}

// ---------------------------------------------------------------------------
// K3 (fused): hidden = relu(N_b @ X), attr_map = sigmoid(c2 . hidden),
//             attr_feature = attr_map * X.   X tile kept in smem (read once).
// grid (13 tiles, 64 batches), 128 threads. Thread layout 16 t-groups x 8
// o-groups, each thread a 4x4 register tile -> 16 FMA per 2 LDS.128.
// ---------------------------------------------------------------------------
__global__ void __launch_bounds__(128, 2)
k3_fused(const float* __restrict__ ef,
         const float* __restrict__ conv2_w,
         float* __restrict__ out_map,
         float* __restrict__ out_feat) {
    extern __shared__ float smem[];
    float* Xs   = smem;                 // [256][64]
    float* Ns   = Xs + CD * TILE;       // [256][32]
    float* red  = Ns + CD * O1;         // [8][64]
    float* amap = red + 8 * TILE;       // [64]

    const int b   = blockIdx.y;
    const int hw0 = blockIdx.x * TILE;
    const int tid = threadIdx.x;

    // Load folded matrix N (32 KB, contiguous, coalesced): 2048 float4 / 128 thr
    {
        const float4* ng  = (const float4*)(g_N + (size_t)b * CD * O1);
        float4*       ns4 = (float4*)Ns;
#pragma unroll
        for (int i = 0; i < 16; i++)
            ns4[tid + i * 128] = ng[tid + i * 128];
    }

    // Load X tile: ef[b, c, hw0 : hw0+64] -> Xs[c][t]. 4096 float4 / 128 thr.
    const float* efb = ef + (size_t)b * CD * HWD;
#pragma unroll
    for (int k = 0; k < 32; k++) {
        int idx = tid + k * 128;          // 0..4095
        int c   = idx >> 4;               // 0..255
        int t   = (idx & 15) * 4;         // 0..60
        float4 v = make_float4(0.f, 0.f, 0.f, 0.f);
        if (hw0 + t < HWD) v = *(const float4*)(efb + (size_t)c * HWD + hw0 + t);
        *(float4*)(Xs + c * TILE + t) = v;
    }
    __syncthreads();

    const int tt = tid & 15;   // t-group: owns t = tt*4 .. tt*4+3
    const int oo = tid >> 4;   // o-group: owns o = oo*4 .. oo*4+3

    float acc[4][4];
#pragma unroll
    for (int i = 0; i < 4; i++)
#pragma unroll
        for (int jj = 0; jj < 4; jj++) acc[i][jj] = 0.f;

#pragma unroll 8
    for (int c = 0; c < CD; c++) {
        float4 xv = *(const float4*)(Xs + c * TILE + tt * 4);
        float4 nv = *(const float4*)(Ns + c * O1 + oo * 4);
        acc[0][0] += nv.x * xv.x; acc[0][1] += nv.x * xv.y;
        acc[0][2] += nv.x * xv.z; acc[0][3] += nv.x * xv.w;
        acc[1][0] += nv.y * xv.x; acc[1][1] += nv.y * xv.y;
        acc[1][2] += nv.y * xv.z; acc[1][3] += nv.y * xv.w;
        acc[2][0] += nv.z * xv.x; acc[2][1] += nv.z * xv.y;
        acc[2][2] += nv.z * xv.z; acc[2][3] += nv.z * xv.w;
        acc[3][0] += nv.w * xv.x; acc[3][1] += nv.w * xv.y;
        acc[3][2] += nv.w * xv.z; acc[3][3] += nv.w * xv.w;
    }

    // relu + conv2 partial over this thread's 4 o's, for its 4 t's
    float c2[4];
#pragma unroll
    for (int i = 0; i < 4; i++) c2[i] = __ldg(conv2_w + oo * 4 + i);

    float p[4] = {0.f, 0.f, 0.f, 0.f};
#pragma unroll
    for (int i = 0; i < 4; i++)
#pragma unroll
        for (int jj = 0; jj < 4; jj++)
            p[jj] += c2[i] * fmaxf(acc[i][jj], 0.f);

#pragma unroll
    for (int jj = 0; jj < 4; jj++) red[oo * TILE + tt * 4 + jj] = p[jj];
    __syncthreads();

    // Reduce 8 o-groups, sigmoid, emit attr_map
    if (tid < TILE) {
        float s = 0.f;
#pragma unroll
        for (int g = 0; g < 8; g++) s += red[g * TILE + tid];
        float am = 1.f / (1.f + expf(-s));
        amap[tid] = am;
        if (hw0 + tid < HWD) out_map[b * HWD + hw0 + tid] = am;
    }
    __syncthreads();

    // attr_feature = attr_map * X, from the smem tile (no second global read)
    float* ofb = out_feat + (size_t)b * CD * HWD;
#pragma unroll
    for (int k = 0; k < 32; k++) {
        int idx = tid + k * 128;
        int c   = idx >> 4;
        int t   = (idx & 15) * 4;
        if (hw0 + t < HWD) {
            float4 v  = *(const float4*)(Xs + c * TILE + t);
            float  a0 = amap[t],     a1 = amap[t + 1];
            float  a2 = amap[t + 2], a3 = amap[t + 3];
            *(float4*)(ofb + (size_t)c * HWD + hw0 + t) =
                make_float4(v.x * a0, v.y * a1, v.z * a2, v.w * a3);
        }
    }
}

// ---------------------------------------------------------------------------
extern "C" void kernel_launch(void* const* d_in, const int* in_sizes, int n_in,
                              void* d_out, int out_size) {
    const float* entity  = (const float*)d_in[0];   // [64,256,28,28]
    const float* attr1h  = (const float*)d_in[1];   // [64,300]
    const float* W_emb   = (const float*)d_in[2];   // [256,300]
    const float* b_emb   = (const float*)d_in[3];   // [256]
    const int*   h1      = (const int*)  d_in[4];   // [256]
    const float* s1      = (const float*)d_in[5];   // [256]
    const int*   h2      = (const int*)  d_in[6];   // [256]
    const float* s2      = (const float*)d_in[7];   // [256]
    const float* conv1_w = (const float*)d_in[8];   // [32,256]
    const float* conv2_w = (const float*)d_in[9];   // [1,32]

    float* out_map  = (float*)d_out;                      // [64,1,28,28]
    float* out_feat = (float*)d_out + (size_t)BD * HWD;   // [64,256,28,28]

    const int k3_smem = (CD * TILE + CD * O1 + 8 * TILE + TILE) * (int)sizeof(float);
    cudaFuncSetAttribute(k3_fused, cudaFuncAttributeMaxDynamicSharedMemorySize, k3_smem);

    k1_sketch<<<BD, 256>>>(attr1h, W_emb, b_emb, h1, s1);
    k2_buildN<<<dim3(BD, 8), 256>>>(conv1_w, h2, s2);
    k3_fused<<<dim3((HWD + TILE - 1) / TILE, BD), 128, k3_smem>>>(entity, conv2_w, out_map, out_feat);
}

// round 4
// speedup vs baseline: 1.3483x; 1.1565x over previous
#include <cuda_runtime.h>
#include <math.h>

#define BD   64
#define CD   256
#define ATTR 300
#define HWD  784
#define O1   32
#define TILE 64

__device__ float g_SX[BD * CD];
__device__ float g_N[BD * CD * O1];

// ---- f32x2 packed helpers (Blackwell FFMA2 via PTX) ------------------------
__device__ __forceinline__ unsigned long long pack2(float a, float b) {
    unsigned long long r;
    asm("mov.b64 %0, {%1, %2};" : "=l"(r)
        : "r"(__float_as_uint(a)), "r"(__float_as_uint(b)));
    return r;
}
__device__ __forceinline__ unsigned long long fma2(unsigned long long a,
                                                   unsigned long long b,
                                                   unsigned long long c) {
    unsigned long long d;
    asm("fma.rn.f32x2 %0, %1, %2, %3;" : "=l"(d) : "l"(a), "l"(b), "l"(c));
    return d;
}
__device__ __forceinline__ float2 unpack2(unsigned long long v) {
    float2 f;
    f.x = __uint_as_float((unsigned)v);
    f.y = __uint_as_float((unsigned)(v >> 32));
    return f;
}

// ---------------------------------------------------------------------------
// K1: emb = attr_one_hot @ W_emb^T + b_emb ; sx = count_sketch(emb, h1, s1)
// Warp w owns j in [32w,32w+32). 4 j's per pass: 40 predicated LDGs issued
// back-to-back (one L2 latency), fixed-trip unrolled, butterfly reduce.
// ---------------------------------------------------------------------------
__global__ void k1_sketch(const float* __restrict__ attr_one_hot,
                          const float* __restrict__ W_emb,
                          const float* __restrict__ b_emb,
                          const int*   __restrict__ h1,
                          const float* __restrict__ s1) {
    __shared__ float attr_sm[320];
    __shared__ float emb_sm[CD];
    __shared__ int   h1_sm[CD];
    __shared__ float s1_sm[CD];

    const int b    = blockIdx.x;
    const int tid  = threadIdx.x;
    const int lane = tid & 31;
    const int wrp  = tid >> 5;

    for (int a = tid; a < ATTR; a += 256) attr_sm[a] = attr_one_hot[b * ATTR + a];
    if (tid < 320 - ATTR + 0) {}               // (attr_sm tail unused)
    if (tid >= ATTR - 256 && tid < 64) {}      // no-op; keep simple
    h1_sm[tid] = h1[tid];
    s1_sm[tid] = s1[tid];
    __syncthreads();

    const int jbase = wrp * 32;
#pragma unroll
    for (int jr = 0; jr < 32; jr += 4) {
        const int j0 = jbase + jr;
        float wv[4][10];
        // issue all 40 loads back-to-back (predicated, MLP ~40)
#pragma unroll
        for (int k = 0; k < 10; k++) {
            const int a  = lane + 32 * k;
            const bool ok = (a < ATTR);
#pragma unroll
            for (int q = 0; q < 4; q++)
                wv[q][k] = ok ? W_emb[(size_t)(j0 + q) * ATTR + a] : 0.f;
        }
        float p0 = 0.f, p1 = 0.f, p2 = 0.f, p3 = 0.f;
#pragma unroll
        for (int k = 0; k < 10; k++) {
            const int a  = lane + 32 * k;
            const float av = (a < ATTR) ? attr_sm[a] : 0.f;
            p0 += av * wv[0][k];
            p1 += av * wv[1][k];
            p2 += av * wv[2][k];
            p3 += av * wv[3][k];
        }
#pragma unroll
        for (int off = 16; off >= 1; off >>= 1) {
            p0 += __shfl_xor_sync(0xFFFFFFFFu, p0, off);
            p1 += __shfl_xor_sync(0xFFFFFFFFu, p1, off);
            p2 += __shfl_xor_sync(0xFFFFFFFFu, p2, off);
            p3 += __shfl_xor_sync(0xFFFFFFFFu, p3, off);
        }
        if (lane == 0) emb_sm[j0 + 0] = p0 + b_emb[j0 + 0];
        if (lane == 1) emb_sm[j0 + 1] = p1 + b_emb[j0 + 1];
        if (lane == 2) emb_sm[j0 + 2] = p2 + b_emb[j0 + 2];
        if (lane == 3) emb_sm[j0 + 3] = p3 + b_emb[j0 + 3];
    }
    __syncthreads();

    // Deterministic count-sketch: thread m scans all j for h1[j]==m.
    const int m = tid;
    float sx = 0.f;
#pragma unroll 8
    for (int jj = 0; jj < CD; jj++)
        sx += (h1_sm[jj] == m) ? s1_sm[jj] * emb_sm[jj] : 0.f;
    g_SX[b * CD + m] = sx;
}

// ---------------------------------------------------------------------------
// K2: M_b[o,m] = sum_j sx_b[j] * conv1_w[o, (m+j) mod 256]
//     N_b[o,c] = s2[c] * M_b[o, h2[c]]
// grid (64, 8 o-groups), 256 threads. Thread = (mq 0..63, oo 0..3): 4 m's,
// one o. Sliding float4 window over padded wext rows (520 -> conflict-free),
// float4 broadcast for sx: 2 LDS.128 + 16 FMA per 4 jj.
// ---------------------------------------------------------------------------
#define WPAD 520
__global__ void k2_buildN(const float* __restrict__ conv1_w,
                          const int*   __restrict__ h2,
                          const float* __restrict__ s2) {
    __shared__ float sx[CD];
    __shared__ float wext[4][WPAD];
    __shared__ float Msm[4][CD];

    const int b   = blockIdx.x;
    const int og  = blockIdx.y;
    const int tid = threadIdx.x;

    sx[tid] = g_SX[b * CD + tid];
#pragma unroll
    for (int oo = 0; oo < 4; oo++) {
        float w = conv1_w[(og * 4 + oo) * CD + tid];
        wext[oo][tid]       = w;
        wext[oo][tid + 256] = w;
    }
    __syncthreads();

    const int mq = tid >> 2;      // 0..63
    const int oo = tid & 3;       // 0..3
    const int m0 = mq * 4;

    float a0 = 0.f, a1 = 0.f, a2 = 0.f, a3 = 0.f;
    float4 cur = *(const float4*)&wext[oo][m0];
#pragma unroll 4
    for (int jj = 0; jj < CD; jj += 4) {
        float4 nxt = *(const float4*)&wext[oo][m0 + jj + 4];
        float4 sv  = *(const float4*)&sx[jj];
        a0 += sv.x * cur.x; a1 += sv.x * cur.y; a2 += sv.x * cur.z; a3 += sv.x * cur.w;
        a0 += sv.y * cur.y; a1 += sv.y * cur.z; a2 += sv.y * cur.w; a3 += sv.y * nxt.x;
        a0 += sv.z * cur.z; a1 += sv.z * cur.w; a2 += sv.z * nxt.x; a3 += sv.z * nxt.y;
        a0 += sv.w * cur.w; a1 += sv.w * nxt.x; a2 += sv.w * nxt.y; a3 += sv.w * nxt.z;
        cur = nxt;
    }
    *(float4*)&Msm[oo][m0] = make_float4(a0, a1, a2, a3);
    __syncthreads();

    const int   c  = tid;
    const int   hc = h2[c];
    const float sc = s2[c];
    float* np = &g_N[((size_t)b * CD + c) * O1 + og * 4];
    *(float4*)np = make_float4(sc * Msm[0][hc], sc * Msm[1][hc],
                               sc * Msm[2][hc], sc * Msm[3][hc]);
}

// ---------------------------------------------------------------------------
// K3 (fused): hidden = relu(N_b @ X), attr_map = sigmoid(c2.hidden),
//             attr_feature = attr_map * X. FFMA2 mainloop, broadcast-friendly
//             lane map: oo = tid&7 (8 o-groups of 4), tt = tid>>3 (16 t-groups
//             of 4). nv: 8 distinct 16B/warp; xv: 4 distinct 16B -> dedup.
// ---------------------------------------------------------------------------
__global__ void __launch_bounds__(128, 2)
k3_fused(const float* __restrict__ ef,
         const float* __restrict__ conv2_w,
         float* __restrict__ out_map,
         float* __restrict__ out_feat) {
    extern __shared__ float smem[];
    float* Xs   = smem;                 // [256][64]
    float* Ns   = Xs + CD * TILE;       // [256][32]
    float* red  = Ns + CD * O1;         // [8][64]
    float* amap = red + 8 * TILE;       // [64]

    const int b   = blockIdx.y;
    const int hw0 = blockIdx.x * TILE;
    const int tid = threadIdx.x;

    // Load N_b (32 KB contiguous)
    {
        const float4* ng  = (const float4*)(g_N + (size_t)b * CD * O1);
        float4*       ns4 = (float4*)Ns;
#pragma unroll
        for (int i = 0; i < 16; i++)
            ns4[tid + i * 128] = ng[tid + i * 128];
    }
    // Load X tile (coalesced float4, zero-padded tail)
    const float* efb = ef + (size_t)b * CD * HWD;
#pragma unroll
    for (int k = 0; k < 32; k++) {
        int idx = tid + k * 128;
        int c   = idx >> 4;
        int t   = (idx & 15) * 4;
        float4 v = make_float4(0.f, 0.f, 0.f, 0.f);
        if (hw0 + t < HWD) v = *(const float4*)(efb + (size_t)c * HWD + hw0 + t);
        *(float4*)(Xs + c * TILE + t) = v;
    }
    __syncthreads();

    const int oo = tid & 7;    // o-group: o = oo*4 .. oo*4+3
    const int tt = tid >> 3;   // t-group: t = tt*4 .. tt*4+3

    unsigned long long acc[4][2];
#pragma unroll
    for (int i = 0; i < 4; i++) { acc[i][0] = 0ull; acc[i][1] = 0ull; }

    const float* xp = Xs + tt * 4;
    const float* np = Ns + oo * 4;
#pragma unroll 4
    for (int c = 0; c < CD; c++) {
        ulonglong2 xv = *(const ulonglong2*)(xp + c * TILE);   // (t0,t1),(t2,t3)
        float4     nv = *(const float4*)(np + c * O1);
        unsigned long long n0 = pack2(nv.x, nv.x);
        unsigned long long n1 = pack2(nv.y, nv.y);
        unsigned long long n2 = pack2(nv.z, nv.z);
        unsigned long long n3 = pack2(nv.w, nv.w);
        acc[0][0] = fma2(n0, xv.x, acc[0][0]); acc[0][1] = fma2(n0, xv.y, acc[0][1]);
        acc[1][0] = fma2(n1, xv.x, acc[1][0]); acc[1][1] = fma2(n1, xv.y, acc[1][1]);
        acc[2][0] = fma2(n2, xv.x, acc[2][0]); acc[2][1] = fma2(n2, xv.y, acc[2][1]);
        acc[3][0] = fma2(n3, xv.x, acc[3][0]); acc[3][1] = fma2(n3, xv.y, acc[3][1]);
    }

    // relu + conv2 partial
    float p[4] = {0.f, 0.f, 0.f, 0.f};
#pragma unroll
    for (int i = 0; i < 4; i++) {
        float  cw  = __ldg(conv2_w + oo * 4 + i);
        float2 a01 = unpack2(acc[i][0]);
        float2 a23 = unpack2(acc[i][1]);
        p[0] += cw * fmaxf(a01.x, 0.f);
        p[1] += cw * fmaxf(a01.y, 0.f);
        p[2] += cw * fmaxf(a23.x, 0.f);
        p[3] += cw * fmaxf(a23.y, 0.f);
    }
#pragma unroll
    for (int jj = 0; jj < 4; jj++) red[oo * TILE + tt * 4 + jj] = p[jj];
    __syncthreads();

    if (tid < TILE) {
        float s = 0.f;
#pragma unroll
        for (int g = 0; g < 8; g++) s += red[g * TILE + tid];
        float am = 1.f / (1.f + expf(-s));
        amap[tid] = am;
        if (hw0 + tid < HWD) out_map[b * HWD + hw0 + tid] = am;
    }
    __syncthreads();

    float* ofb = out_feat + (size_t)b * CD * HWD;
#pragma unroll
    for (int k = 0; k < 32; k++) {
        int idx = tid + k * 128;
        int c   = idx >> 4;
        int t   = (idx & 15) * 4;
        if (hw0 + t < HWD) {
            float4 v  = *(const float4*)(Xs + c * TILE + t);
            float  a0 = amap[t],     a1 = amap[t + 1];
            float  a2 = amap[t + 2], a3 = amap[t + 3];
            *(float4*)(ofb + (size_t)c * HWD + hw0 + t) =
                make_float4(v.x * a0, v.y * a1, v.z * a2, v.w * a3);
        }
    }
}

// ---------------------------------------------------------------------------
extern "C" void kernel_launch(void* const* d_in, const int* in_sizes, int n_in,
                              void* d_out, int out_size) {
    const float* entity  = (const float*)d_in[0];
    const float* attr1h  = (const float*)d_in[1];
    const float* W_emb   = (const float*)d_in[2];
    const float* b_emb   = (const float*)d_in[3];
    const int*   h1      = (const int*)  d_in[4];
    const float* s1      = (const float*)d_in[5];
    const int*   h2      = (const int*)  d_in[6];
    const float* s2      = (const float*)d_in[7];
    const float* conv1_w = (const float*)d_in[8];
    const float* conv2_w = (const float*)d_in[9];

    float* out_map  = (float*)d_out;
    float* out_feat = (float*)d_out + (size_t)BD * HWD;

    const int k3_smem = (CD * TILE + CD * O1 + 8 * TILE + TILE) * (int)sizeof(float);
    cudaFuncSetAttribute(k3_fused, cudaFuncAttributeMaxDynamicSharedMemorySize, k3_smem);

    k1_sketch<<<BD, 256>>>(attr1h, W_emb, b_emb, h1, s1);
    k2_buildN<<<dim3(BD, 8), 256>>>(conv1_w, h2, s2);
    k3_fused<<<dim3((HWD + TILE - 1) / TILE, BD), 128, k3_smem>>>(entity, conv2_w, out_map, out_feat);
}

// round 5
// speedup vs baseline: 1.4793x; 1.0971x over previous
#include <cuda_runtime.h>
#include <math.h>

#define BD   64
#define CD   256
#define ATTR 300
#define HWD  784
#define O1   32
#define TILE 64

__device__ float g_EMB[BD * CD];         // per-batch embedding
__device__ float g_N[BD * CD * O1];      // folded [b][c][o] matrix

// ---- f32x2 packed helpers (Blackwell FFMA2 via PTX) ------------------------
__device__ __forceinline__ unsigned long long pack2(float a, float b) {
    unsigned long long r;
    asm("mov.b64 %0, {%1, %2};" : "=l"(r)
        : "r"(__float_as_uint(a)), "r"(__float_as_uint(b)));
    return r;
}
__device__ __forceinline__ unsigned long long fma2(unsigned long long a,
                                                   unsigned long long b,
                                                   unsigned long long c) {
    unsigned long long d;
    asm("fma.rn.f32x2 %0, %1, %2, %3;" : "=l"(d) : "l"(a), "l"(b), "l"(c));
    return d;
}
__device__ __forceinline__ float2 unpack2(unsigned long long v) {
    float2 f;
    f.x = __uint_as_float((unsigned)v);
    f.y = __uint_as_float((unsigned)(v >> 32));
    return f;
}

// ---------------------------------------------------------------------------
// K1: emb[b, j] = attr_one_hot[b] . W_emb[j] + b_emb[j]
// grid (64 batches, 8 j-groups), 128 threads = 4 warps. Warp w owns 8 j's,
// processed as 2 quads: 40 coalesced LDGs issued back-to-back per quad
// (one L2 latency), then FMA + butterfly reduce. 2048 warps chip-wide.
// ---------------------------------------------------------------------------
__global__ void __launch_bounds__(128, 4)
k1_emb(const float* __restrict__ attr_one_hot,
       const float* __restrict__ W_emb,
       const float* __restrict__ b_emb) {
    __shared__ float attr_sm[ATTR];

    const int b    = blockIdx.x;
    const int jg   = blockIdx.y;            // 0..7
    const int tid  = threadIdx.x;
    const int lane = tid & 31;
    const int wrp  = tid >> 5;              // 0..3

    for (int a = tid; a < ATTR; a += 128) attr_sm[a] = attr_one_hot[b * ATTR + a];
    __syncthreads();

    const int jbase = jg * 32 + wrp * 8;
#pragma unroll
    for (int pass = 0; pass < 2; pass++) {
        const int j0 = jbase + pass * 4;
        float wv[4][10];
        // 40 loads issued back-to-back (predicated tail), MLP ~40
#pragma unroll
        for (int k = 0; k < 10; k++) {
            const int  a  = lane + 32 * k;
            const bool ok = (a < ATTR);
#pragma unroll
            for (int q = 0; q < 4; q++)
                wv[q][k] = ok ? W_emb[(size_t)(j0 + q) * ATTR + a] : 0.f;
        }
        float p0 = 0.f, p1 = 0.f, p2 = 0.f, p3 = 0.f;
#pragma unroll
        for (int k = 0; k < 10; k++) {
            const int   a  = lane + 32 * k;
            const float av = (a < ATTR) ? attr_sm[a] : 0.f;
            p0 += av * wv[0][k];
            p1 += av * wv[1][k];
            p2 += av * wv[2][k];
            p3 += av * wv[3][k];
        }
#pragma unroll
        for (int off = 16; off >= 1; off >>= 1) {
            p0 += __shfl_xor_sync(0xFFFFFFFFu, p0, off);
            p1 += __shfl_xor_sync(0xFFFFFFFFu, p1, off);
            p2 += __shfl_xor_sync(0xFFFFFFFFu, p2, off);
            p3 += __shfl_xor_sync(0xFFFFFFFFu, p3, off);
        }
        if (lane == 0) g_EMB[b * CD + j0 + 0] = p0 + b_emb[j0 + 0];
        if (lane == 1) g_EMB[b * CD + j0 + 1] = p1 + b_emb[j0 + 1];
        if (lane == 2) g_EMB[b * CD + j0 + 2] = p2 + b_emb[j0 + 2];
        if (lane == 3) g_EMB[b * CD + j0 + 3] = p3 + b_emb[j0 + 3];
    }
}

// ---------------------------------------------------------------------------
// K2: sx = count_sketch(emb, h1, s1)  (recomputed per block, parallel-cheap)
//     M_b[o,m] = sum_j sx[j] * conv1_w[o, (m+j) mod 256]
//     N_b[o,c] = s2[c] * M_b[o, h2[c]]
// grid (64, 8 og), 256 threads. Sliding float4 window, conflict-free padded
// rows; thread = (mq, oo): 4 m's, 1 o.
// ---------------------------------------------------------------------------
#define WPAD 520
__global__ void k2_buildN(const float* __restrict__ conv1_w,
                          const int*   __restrict__ h1,
                          const float* __restrict__ s1,
                          const int*   __restrict__ h2,
                          const float* __restrict__ s2) {
    __shared__ float emb_sm[CD];
    __shared__ int   h1_sm[CD];
    __shared__ float s1_sm[CD];
    __shared__ float sx[CD];
    __shared__ float wext[4][WPAD];
    __shared__ float Msm[4][CD];

    const int b   = blockIdx.x;
    const int og  = blockIdx.y;
    const int tid = threadIdx.x;

    emb_sm[tid] = g_EMB[b * CD + tid];
    h1_sm[tid]  = h1[tid];
    s1_sm[tid]  = s1[tid];
#pragma unroll
    for (int oo = 0; oo < 4; oo++) {
        float w = conv1_w[(og * 4 + oo) * CD + tid];
        wext[oo][tid]       = w;
        wext[oo][tid + 256] = w;
    }
    __syncthreads();

    // deterministic count-sketch: thread m scans all j
    {
        const int m  = tid;
        float     sv = 0.f;
#pragma unroll 8
        for (int jj = 0; jj < CD; jj++)
            sv += (h1_sm[jj] == m) ? s1_sm[jj] * emb_sm[jj] : 0.f;
        sx[m] = sv;
    }
    __syncthreads();

    const int mq = tid >> 2;
    const int oo = tid & 3;
    const int m0 = mq * 4;

    float a0 = 0.f, a1 = 0.f, a2 = 0.f, a3 = 0.f;
    float4 cur = *(const float4*)&wext[oo][m0];
#pragma unroll 4
    for (int jj = 0; jj < CD; jj += 4) {
        float4 nxt = *(const float4*)&wext[oo][m0 + jj + 4];
        float4 sv  = *(const float4*)&sx[jj];
        a0 += sv.x * cur.x; a1 += sv.x * cur.y; a2 += sv.x * cur.z; a3 += sv.x * cur.w;
        a0 += sv.y * cur.y; a1 += sv.y * cur.z; a2 += sv.y * cur.w; a3 += sv.y * nxt.x;
        a0 += sv.z * cur.z; a1 += sv.z * cur.w; a2 += sv.z * nxt.x; a3 += sv.z * nxt.y;
        a0 += sv.w * cur.w; a1 += sv.w * nxt.x; a2 += sv.w * nxt.y; a3 += sv.w * nxt.z;
        cur = nxt;
    }
    *(float4*)&Msm[oo][m0] = make_float4(a0, a1, a2, a3);
    __syncthreads();

    const int   c  = tid;
    const int   hc = h2[c];
    const float sc = s2[c];
    float* np = &g_N[((size_t)b * CD + c) * O1 + og * 4];
    *(float4*)np = make_float4(sc * Msm[0][hc], sc * Msm[1][hc],
                               sc * Msm[2][hc], sc * Msm[3][hc]);
}

// ---------------------------------------------------------------------------
// K3 (fused): hidden = relu(N_b @ X), attr_map = sigmoid(c2.hidden),
//             attr_feature = attr_map * X. FFMA2 mainloop.
// ---------------------------------------------------------------------------
__global__ void __launch_bounds__(128, 2)
k3_fused(const float* __restrict__ ef,
         const float* __restrict__ conv2_w,
         float* __restrict__ out_map,
         float* __restrict__ out_feat) {
    extern __shared__ float smem[];
    float* Xs   = smem;                 // [256][64]
    float* Ns   = Xs + CD * TILE;       // [256][32]
    float* red  = Ns + CD * O1;         // [8][64]
    float* amap = red + 8 * TILE;       // [64]

    const int b   = blockIdx.y;
    const int hw0 = blockIdx.x * TILE;
    const int tid = threadIdx.x;

    {
        const float4* ng  = (const float4*)(g_N + (size_t)b * CD * O1);
        float4*       ns4 = (float4*)Ns;
#pragma unroll
        for (int i = 0; i < 16; i++)
            ns4[tid + i * 128] = ng[tid + i * 128];
    }
    const float* efb = ef + (size_t)b * CD * HWD;
#pragma unroll
    for (int k = 0; k < 32; k++) {
        int idx = tid + k * 128;
        int c   = idx >> 4;
        int t   = (idx & 15) * 4;
        float4 v = make_float4(0.f, 0.f, 0.f, 0.f);
        if (hw0 + t < HWD) v = *(const float4*)(efb + (size_t)c * HWD + hw0 + t);
        *(float4*)(Xs + c * TILE + t) = v;
    }
    __syncthreads();

    const int oo = tid & 7;
    const int tt = tid >> 3;

    unsigned long long acc[4][2];
#pragma unroll
    for (int i = 0; i < 4; i++) { acc[i][0] = 0ull; acc[i][1] = 0ull; }

    const float* xp = Xs + tt * 4;
    const float* np = Ns + oo * 4;
#pragma unroll 4
    for (int c = 0; c < CD; c++) {
        ulonglong2 xv = *(const ulonglong2*)(xp + c * TILE);
        float4     nv = *(const float4*)(np + c * O1);
        unsigned long long n0 = pack2(nv.x, nv.x);
        unsigned long long n1 = pack2(nv.y, nv.y);
        unsigned long long n2 = pack2(nv.z, nv.z);
        unsigned long long n3 = pack2(nv.w, nv.w);
        acc[0][0] = fma2(n0, xv.x, acc[0][0]); acc[0][1] = fma2(n0, xv.y, acc[0][1]);
        acc[1][0] = fma2(n1, xv.x, acc[1][0]); acc[1][1] = fma2(n1, xv.y, acc[1][1]);
        acc[2][0] = fma2(n2, xv.x, acc[2][0]); acc[2][1] = fma2(n2, xv.y, acc[2][1]);
        acc[3][0] = fma2(n3, xv.x, acc[3][0]); acc[3][1] = fma2(n3, xv.y, acc[3][1]);
    }

    float p[4] = {0.f, 0.f, 0.f, 0.f};
#pragma unroll
    for (int i = 0; i < 4; i++) {
        float  cw  = __ldg(conv2_w + oo * 4 + i);
        float2 a01 = unpack2(acc[i][0]);
        float2 a23 = unpack2(acc[i][1]);
        p[0] += cw * fmaxf(a01.x, 0.f);
        p[1] += cw * fmaxf(a01.y, 0.f);
        p[2] += cw * fmaxf(a23.x, 0.f);
        p[3] += cw * fmaxf(a23.y, 0.f);
    }
#pragma unroll
    for (int jj = 0; jj < 4; jj++) red[oo * TILE + tt * 4 + jj] = p[jj];
    __syncthreads();

    if (tid < TILE) {
        float s = 0.f;
#pragma unroll
        for (int g = 0; g < 8; g++) s += red[g * TILE + tid];
        float am = 1.f / (1.f + expf(-s));
        amap[tid] = am;
        if (hw0 + tid < HWD) out_map[b * HWD + hw0 + tid] = am;
    }
    __syncthreads();

    float* ofb = out_feat + (size_t)b * CD * HWD;
#pragma unroll
    for (int k = 0; k < 32; k++) {
        int idx = tid + k * 128;
        int c   = idx >> 4;
        int t   = (idx & 15) * 4;
        if (hw0 + t < HWD) {
            float4 v  = *(const float4*)(Xs + c * TILE + t);
            float  a0 = amap[t],     a1 = amap[t + 1];
            float  a2 = amap[t + 2], a3 = amap[t + 3];
            *(float4*)(ofb + (size_t)c * HWD + hw0 + t) =
                make_float4(v.x * a0, v.y * a1, v.z * a2, v.w * a3);
        }
    }
}

// ---------------------------------------------------------------------------
extern "C" void kernel_launch(void* const* d_in, const int* in_sizes, int n_in,
                              void* d_out, int out_size) {
    const float* entity  = (const float*)d_in[0];
    const float* attr1h  = (const float*)d_in[1];
    const float* W_emb   = (const float*)d_in[2];
    const float* b_emb   = (const float*)d_in[3];
    const int*   h1      = (const int*)  d_in[4];
    const float* s1      = (const float*)d_in[5];
    const int*   h2      = (const int*)  d_in[6];
    const float* s2      = (const float*)d_in[7];
    const float* conv1_w = (const float*)d_in[8];
    const float* conv2_w = (const float*)d_in[9];

    float* out_map  = (float*)d_out;
    float* out_feat = (float*)d_out + (size_t)BD * HWD;

    const int k3_smem = (CD * TILE + CD * O1 + 8 * TILE + TILE) * (int)sizeof(float);
    cudaFuncSetAttribute(k3_fused, cudaFuncAttributeMaxDynamicSharedMemorySize, k3_smem);

    k1_emb<<<dim3(BD, 8), 128>>>(attr1h, W_emb, b_emb);
    k2_buildN<<<dim3(BD, 8), 256>>>(conv1_w, h1, s1, h2, s2);
    k3_fused<<<dim3((HWD + TILE - 1) / TILE, BD), 128, k3_smem>>>(entity, conv2_w, out_map, out_feat);
}